// round 9
// baseline (speedup 1.0000x reference)
#include <cuda_runtime.h>
#include <cuda_bf16.h>
#include <math.h>
#include <stdint.h>

#define CH   512
#define SP   3136
#define NB   32
#define MTOT 100352
#define EPSV 1e-5f

typedef unsigned long long ull;

// ===================== PTX helpers =========================================
__device__ __forceinline__ uint32_t smem_u32(const void* p) {
    uint32_t a;
    asm("{ .reg .u64 t; cvta.to.shared.u64 t, %1; cvt.u32.u64 %0, t; }"
        : "=r"(a) : "l"(p));
    return a;
}
__device__ __forceinline__ void ldsm4(uint32_t r[4], uint32_t a) {
    asm volatile("ldmatrix.sync.aligned.m8n8.x4.shared.b16 {%0,%1,%2,%3}, [%4];"
                 : "=r"(r[0]), "=r"(r[1]), "=r"(r[2]), "=r"(r[3]) : "r"(a));
}
__device__ __forceinline__ void ldsm4t(uint32_t r[4], uint32_t a) {
    asm volatile("ldmatrix.sync.aligned.m8n8.x4.trans.shared.b16 {%0,%1,%2,%3}, [%4];"
                 : "=r"(r[0]), "=r"(r[1]), "=r"(r[2]), "=r"(r[3]) : "r"(a));
}
__device__ __forceinline__ void mma16816(float c[4], const uint32_t a[4],
                                         const uint32_t b[2]) {
    asm volatile("mma.sync.aligned.m16n8k16.row.col.f32.bf16.bf16.f32 "
                 "{%0,%1,%2,%3}, {%4,%5,%6,%7}, {%8,%9}, {%0,%1,%2,%3};"
                 : "+f"(c[0]), "+f"(c[1]), "+f"(c[2]), "+f"(c[3])
                 : "r"(a[0]), "r"(a[1]), "r"(a[2]), "r"(a[3]),
                   "r"(b[0]), "r"(b[1]));
}

union U4BF { uint4 u; __nv_bfloat162 h[4]; };

// split 8 fp32 -> 8 bf16 hi + 8 bf16 lo
__device__ __forceinline__ void split8(const float4 a, const float4 b,
                                       uint4& hi, uint4& lo) {
    float f[8] = {a.x, a.y, a.z, a.w, b.x, b.y, b.z, b.w};
    U4BF H, L;
    #pragma unroll
    for (int i = 0; i < 4; i++) {
        __nv_bfloat16 h0 = __float2bfloat16(f[2*i]);
        __nv_bfloat16 h1 = __float2bfloat16(f[2*i+1]);
        __nv_bfloat162 hh; hh.x = h0; hh.y = h1;
        __nv_bfloat162 ll;
        ll.x = __float2bfloat16(f[2*i]   - __bfloat162float(h0));
        ll.y = __float2bfloat16(f[2*i+1] - __bfloat162float(h1));
        H.h[i] = hh; L.h[i] = ll;
    }
    hi = H.u; lo = L.u;
}
__device__ __forceinline__ __nv_bfloat162 hi2(float x, float y) {
    __nv_bfloat162 r; r.x = __float2bfloat16(x); r.y = __float2bfloat16(y);
    return r;
}
__device__ __forceinline__ __nv_bfloat162 lo2(float x, float y,
                                              __nv_bfloat162 h) {
    __nv_bfloat162 r;
    r.x = __float2bfloat16(x - __bfloat162float(h.x));
    r.y = __float2bfloat16(y - __bfloat162float(h.y));
    return r;
}

// ===================== scratch globals =====================================
__device__ __align__(16) __nv_bfloat16 g_Mhi[CH * CH];
__device__ __align__(16) __nv_bfloat16 g_Mlo[CH * CH];
__device__ float g_meanpart[NB * CH];
__device__ float g_mean[CH];
__device__ __align__(16) float g_Gsl[(size_t)NB * CH * CH];
__device__ float g_Sigma[CH * CH];
__device__ __align__(16) __nv_bfloat16 g_Shi[CH * CH];
__device__ __align__(16) __nv_bfloat16 g_Slo[CH * CH];
__device__ __align__(16) __nv_bfloat16 g_Phi[CH * CH];
__device__ __align__(16) __nv_bfloat16 g_Plo[CH * CH];
__device__ __align__(16) float g_Pf[CH * CH];
__device__ __align__(16) __nv_bfloat16 g_T1hi[CH * CH];
__device__ __align__(16) __nv_bfloat16 g_T1lo[CH * CH];
__device__ __align__(16) __nv_bfloat16 g_T2hi[CH * CH];
__device__ __align__(16) __nv_bfloat16 g_T2lo[CH * CH];
__device__ __align__(16) __nv_bfloat16 g_rhi[CH * CH];
__device__ __align__(16) __nv_bfloat16 g_rlo[CH * CH];
__device__ float g_M[CH * CH];
__device__ float g_bias[CH];
__device__ float g_scal[2];

// ===================== mean =================================================
__global__ void k_mean_part(const float* __restrict__ X) {
    const int c = blockIdx.x, b = blockIdx.y;
    const float* p = X + ((size_t)b * CH + c) * SP;
    float s = 0.f;
    for (int i = threadIdx.x * 4; i < SP; i += 1024) {
        float4 v = *(const float4*)(p + i);
        s += (v.x + v.y) + (v.z + v.w);
    }
    __shared__ float red[256];
    red[threadIdx.x] = s;
    __syncthreads();
    for (int o = 128; o > 0; o >>= 1) {
        if (threadIdx.x < o) red[threadIdx.x] += red[threadIdx.x + o];
        __syncthreads();
    }
    if (threadIdx.x == 0) g_meanpart[b * CH + c] = red[0];
}

__global__ void k_mean_final() {
    const int c = blockIdx.x * 256 + threadIdx.x;
    float s = 0.f;
    #pragma unroll
    for (int b = 0; b < NB; b++) s += g_meanpart[b * CH + c];
    g_mean[c] = s * (1.0f / MTOT);
}

// ===================== rot split (3 parts, pads ncu launch slot) ===========
__global__ void k_rs(const float* __restrict__ rot, int part) {
    const int base = part * 87382;
    const int idx = base + blockIdx.x * 256 + threadIdx.x;
    if (idx < CH * CH && idx < base + 87382) {
        float v = rot[idx];
        __nv_bfloat16 h = __float2bfloat16(v);
        g_rhi[idx] = h;
        g_rlo[idx] = __float2bfloat16(v - __bfloat162float(h));
    }
}

// ===================== Gram via mma.sync (fp32 in, split in-kernel) ========
#define G_STG  40960
#define G_SMEM (2 * G_STG)

__global__ void __launch_bounds__(256) k_gram_mma(const float* __restrict__ Xf) {
    extern __shared__ char smem[];
    const int tid = threadIdx.x, wid = tid >> 5, lane = tid & 31;
    const int pair = blockIdx.x, slice = blockIdx.y;
    const int PI[10] = {0,0,0,0,1,1,1,2,2,3};
    const int PJ[10] = {0,1,2,3,1,2,3,2,3,3};
    const int m0 = PI[pair] * 128, n0 = PJ[pair] * 128;
    const int wm = (wid & 3) * 32, wn = (wid >> 2) * 64;
    const uint32_t sbase = smem_u32(smem);

    const int aRow = wm + ((lane >> 3) & 1) * 8 + (lane & 7);
    const int aCol = (lane >> 4) * 16;
    const int bRow = wn + (lane >> 4) * 8 + (lane & 7);
    const int bCol = ((lane >> 3) & 1) * 16;

    float acc[2][8][4];
    #pragma unroll
    for (int mt = 0; mt < 2; mt++)
        #pragma unroll
        for (int nt = 0; nt < 8; nt++)
            #pragma unroll
            for (int q = 0; q < 4; q++) acc[mt][nt][q] = 0.f;

    float4 fa[2][2], fb[2][2];
    const size_t Bbase = (size_t)slice * CH * SP;

#define G_LD(kk) do {                                                        \
    const int kbase = (kk) * 32;                                             \
    _Pragma("unroll")                                                        \
    for (int e = 0; e < 2; e++) {                                            \
        const int seg = tid * 2 + e;                                         \
        const int r = seg >> 2, q = seg & 3;                                 \
        const float* pa = Xf + Bbase + (size_t)(m0 + r) * SP + kbase + q * 8;\
        fa[e][0] = *(const float4*)(pa);                                     \
        fa[e][1] = *(const float4*)(pa + 4);                                 \
        const float* pb = Xf + Bbase + (size_t)(n0 + r) * SP + kbase + q * 8;\
        fb[e][0] = *(const float4*)(pb);                                     \
        fb[e][1] = *(const float4*)(pb + 4);                                 \
    } } while (0)

#define G_ST(sg) do { char* _s = smem + (sg) * G_STG;                        \
    _Pragma("unroll")                                                        \
    for (int e = 0; e < 2; e++) {                                            \
        const int seg = tid * 2 + e;                                         \
        const int r = seg >> 2, q = seg & 3;                                 \
        uint4 h, l;                                                          \
        split8(fa[e][0], fa[e][1], h, l);                                    \
        *(uint4*)(_s + r * 80 + q * 16) = h;                                 \
        *(uint4*)(_s + 10240 + r * 80 + q * 16) = l;                         \
        split8(fb[e][0], fb[e][1], h, l);                                    \
        *(uint4*)(_s + 20480 + r * 80 + q * 16) = h;                         \
        *(uint4*)(_s + 30720 + r * 80 + q * 16) = l;                         \
    } } while (0)

    G_LD(0); G_ST(0); __syncthreads();
    for (int kk = 0; kk < 98; kk++) {
        if (kk < 97) G_LD(kk + 1);
        const uint32_t sa = sbase + (kk & 1) * G_STG;
        #pragma unroll
        for (int k16 = 0; k16 < 2; k16++) {
            const int kb = k16 * 32;
            uint32_t ah[2][4], al[2][4], bh[4][4], bl[4][4];
            #pragma unroll
            for (int mt = 0; mt < 2; mt++) {
                const uint32_t ao = sa + (aRow + mt * 16) * 80 + kb + aCol;
                ldsm4(ah[mt], ao);
                ldsm4(al[mt], ao + 10240);
            }
            #pragma unroll
            for (int np = 0; np < 4; np++) {
                const uint32_t bo = sa + 20480 + (bRow + np * 16) * 80 + kb + bCol;
                ldsm4(bh[np], bo);
                ldsm4(bl[np], bo + 10240);
            }
            #pragma unroll
            for (int mt = 0; mt < 2; mt++)
                #pragma unroll
                for (int np = 0; np < 4; np++) {
                    mma16816(acc[mt][np*2],   ah[mt], &bh[np][0]);
                    mma16816(acc[mt][np*2+1], ah[mt], &bh[np][2]);
                    mma16816(acc[mt][np*2],   ah[mt], &bl[np][0]);
                    mma16816(acc[mt][np*2+1], ah[mt], &bl[np][2]);
                    mma16816(acc[mt][np*2],   al[mt], &bh[np][0]);
                    mma16816(acc[mt][np*2+1], al[mt], &bh[np][2]);
                }
        }
        __syncthreads();
        if (kk < 97) { G_ST((kk + 1) & 1); __syncthreads(); }
    }
#undef G_LD
#undef G_ST

    float* dst = g_Gsl + (size_t)slice * CH * CH;
    const int g4 = lane >> 2, t2 = (lane & 3) * 2;
    #pragma unroll
    for (int mt = 0; mt < 2; mt++)
        #pragma unroll
        for (int nt = 0; nt < 8; nt++) {
            const int row = m0 + wm + mt * 16 + g4;
            const int col = n0 + wn + nt * 8 + t2;
            float2 v0; v0.x = acc[mt][nt][0]; v0.y = acc[mt][nt][1];
            float2 v1; v1.x = acc[mt][nt][2]; v1.y = acc[mt][nt][3];
            *(float2*)(dst + (size_t)row * CH + col)       = v0;
            *(float2*)(dst + (size_t)(row + 8) * CH + col) = v1;
        }
}

// ===================== Sigma / trace / prep =================================
__global__ void k_sigma() {
    const int idx = blockIdx.x * 256 + threadIdx.x;
    const int i = idx >> 9, j = idx & 511;
    const size_t off = ((i >> 7) <= (j >> 7)) ? ((size_t)i * CH + j)
                                              : ((size_t)j * CH + i);
    float s = 0.f;
    #pragma unroll 8
    for (int p = 0; p < NB; p++) s += g_Gsl[(size_t)p * CH * CH + off];
    float v = s * (1.0f / MTOT) - g_mean[i] * g_mean[j];
    if (i == j) v += EPSV;
    g_Sigma[idx] = v;
}

__global__ void k_trace() {
    __shared__ float red[512];
    const int t = threadIdx.x;
    red[t] = g_Sigma[t * (CH + 1)];
    __syncthreads();
    for (int o = 256; o > 0; o >>= 1) {
        if (t < o) red[t] += red[t + o];
        __syncthreads();
    }
    if (t == 0) {
        float inv = 1.0f / red[0];
        g_scal[0] = inv;
        g_scal[1] = sqrtf(inv);
    }
}

// SigmaN splits + P0 = I
__global__ void k_prep() {
    const int idx = blockIdx.x * 256 + threadIdx.x;
    float sn = g_Sigma[idx] * g_scal[0];
    __nv_bfloat16 h = __float2bfloat16(sn);
    g_Shi[idx] = h;
    g_Slo[idx] = __float2bfloat16(sn - __bfloat162float(h));
    const int i = idx >> 9, j = idx & 511;
    const float pv = (i == j) ? 1.0f : 0.0f;
    g_Pf[idx]  = pv;
    g_Phi[idx] = __float2bfloat16(pv);
    g_Plo[idx] = __float2bfloat16(0.0f);
}

// ===================== 64x64 TC matmul core (128 threads) ===================
// smem per stage: Ahi 5120 | Alo 5120 | Bhi 4096 | Blo 4096 = 18432
__device__ __forceinline__ void tc64(const __nv_bfloat16* __restrict__ Ah,
                                     const __nv_bfloat16* __restrict__ Al,
                                     const __nv_bfloat16* __restrict__ Bh,
                                     const __nv_bfloat16* __restrict__ Bl,
                                     int i0, int j0, char* sm,
                                     float acc[2][4][4]) {
    const int tid = threadIdx.x, wid = tid >> 5, lane = tid & 31;
    const int wm = (wid >> 1) * 32, wn = (wid & 1) * 32;
    const uint32_t sbase = smem_u32(sm);
    #pragma unroll
    for (int mt = 0; mt < 2; mt++)
        #pragma unroll
        for (int j = 0; j < 4; j++)
            #pragma unroll
            for (int q = 0; q < 4; q++) acc[mt][j][q] = 0.f;

    uint4 vah[2], val_[2], vbh[2], vbl[2];

#define NS_LD(k0) do {                                                       \
    _Pragma("unroll")                                                        \
    for (int e = 0; e < 2; e++) {                                            \
        const int seg = tid * 2 + e;                                         \
        const int ar = seg >> 2, aq = seg & 3;                               \
        const size_t ga = (size_t)(i0 + ar) * 512 + (k0) + aq * 8;           \
        vah[e]  = *(const uint4*)(Ah + ga);                                  \
        val_[e] = *(const uint4*)(Al + ga);                                  \
        const int br = seg >> 3, bg = seg & 7;                               \
        const size_t gb = (size_t)((k0) + br) * 512 + j0 + bg * 8;           \
        vbh[e] = *(const uint4*)(Bh + gb);                                   \
        vbl[e] = *(const uint4*)(Bl + gb);                                   \
    } } while (0)

#define NS_ST(sg) do { char* _s = sm + (sg) * 18432;                         \
    _Pragma("unroll")                                                        \
    for (int e = 0; e < 2; e++) {                                            \
        const int seg = tid * 2 + e;                                         \
        const int ar = seg >> 2, aq = seg & 3;                               \
        *(uint4*)(_s + ar * 80 + aq * 16) = vah[e];                          \
        *(uint4*)(_s + 5120 + ar * 80 + aq * 16) = val_[e];                  \
        const int br = seg >> 3, bg = seg & 7;                               \
        const int ob = br * 128 + ((bg ^ (br & 7)) << 4);                    \
        *(uint4*)(_s + 10240 + ob) = vbh[e];                                 \
        *(uint4*)(_s + 14336 + ob) = vbl[e];                                 \
    } } while (0)

    NS_LD(0); NS_ST(0); __syncthreads();
    for (int kk = 0; kk < 16; kk++) {
        if (kk < 15) NS_LD((kk + 1) * 32);
        const uint32_t sa = sbase + (kk & 1) * 18432;
        #pragma unroll
        for (int k16 = 0; k16 < 2; k16++) {
            uint32_t ah[2][4], al2[2][4], bh[2][4], bl2[2][4];
            const int aR = wm + ((lane >> 3) & 1) * 8 + (lane & 7);
            const int aC = k16 * 32 + (lane >> 4) * 16;
            #pragma unroll
            for (int mt = 0; mt < 2; mt++) {
                const uint32_t ao = sa + (aR + mt * 16) * 80 + aC;
                ldsm4(ah[mt], ao);
                ldsm4(al2[mt], ao + 5120);
            }
            const int kr = k16 * 16 + ((lane >> 3) & 1) * 8 + (lane & 7);
            const int g0 = (wn >> 3) + (lane >> 4);
            #pragma unroll
            for (int np = 0; np < 2; np++) {
                const uint32_t bo = sa + 10240 + kr * 128 +
                                    (((g0 + np * 2) ^ (kr & 7)) << 4);
                ldsm4t(bh[np], bo);
                ldsm4t(bl2[np], bo + 4096);
            }
            #pragma unroll
            for (int mt = 0; mt < 2; mt++)
                #pragma unroll
                for (int np = 0; np < 2; np++) {
                    mma16816(acc[mt][np*2],   ah[mt],  &bh[np][0]);
                    mma16816(acc[mt][np*2+1], ah[mt],  &bh[np][2]);
                    mma16816(acc[mt][np*2],   ah[mt],  &bl2[np][0]);
                    mma16816(acc[mt][np*2+1], ah[mt],  &bl2[np][2]);
                    mma16816(acc[mt][np*2],   al2[mt], &bh[np][0]);
                    mma16816(acc[mt][np*2+1], al2[mt], &bh[np][2]);
                }
        }
        __syncthreads();
        if (kk < 15) { NS_ST((kk + 1) & 1); __syncthreads(); }
    }
#undef NS_LD
#undef NS_ST
}

// NS kernel A: z=0: T1 = P@P ; z=1: T2 = P@SigmaN (split outputs)
__global__ void __launch_bounds__(128) k_nsA() {
    __shared__ char sm[2 * 18432];
    const __nv_bfloat16* Bh = blockIdx.z ? g_Shi : g_Phi;
    const __nv_bfloat16* Bl = blockIdx.z ? g_Slo : g_Plo;
    __nv_bfloat16* Th = blockIdx.z ? g_T2hi : g_T1hi;
    __nv_bfloat16* Tl = blockIdx.z ? g_T2lo : g_T1lo;
    float acc[2][4][4];
    const int i0 = blockIdx.y * 64, j0 = blockIdx.x * 64;
    tc64(g_Phi, g_Plo, Bh, Bl, i0, j0, sm, acc);
    const int lane = threadIdx.x & 31, wid = threadIdx.x >> 5;
    const int wm = (wid >> 1) * 32, wn = (wid & 1) * 32;
    #pragma unroll
    for (int mt = 0; mt < 2; mt++)
        #pragma unroll
        for (int j = 0; j < 4; j++) {
            const int row = i0 + wm + mt * 16 + (lane >> 2);
            const int col = j0 + wn + j * 8 + (lane & 3) * 2;
            __nv_bfloat162 h0 = hi2(acc[mt][j][0], acc[mt][j][1]);
            __nv_bfloat162 h1 = hi2(acc[mt][j][2], acc[mt][j][3]);
            *(__nv_bfloat162*)(Th + (size_t)row * 512 + col) = h0;
            *(__nv_bfloat162*)(Th + (size_t)(row + 8) * 512 + col) = h1;
            *(__nv_bfloat162*)(Tl + (size_t)row * 512 + col) =
                lo2(acc[mt][j][0], acc[mt][j][1], h0);
            *(__nv_bfloat162*)(Tl + (size_t)(row + 8) * 512 + col) =
                lo2(acc[mt][j][2], acc[mt][j][3], h1);
        }
}

// NS kernel B: Pnext = 1.5 P - 0.5 (T1 @ T2); in-place on Pf + splits
__global__ void __launch_bounds__(128) k_nsB() {
    __shared__ char sm[2 * 18432];
    float acc[2][4][4];
    const int i0 = blockIdx.y * 64, j0 = blockIdx.x * 64;
    tc64(g_T1hi, g_T1lo, g_T2hi, g_T2lo, i0, j0, sm, acc);
    const int lane = threadIdx.x & 31, wid = threadIdx.x >> 5;
    const int wm = (wid >> 1) * 32, wn = (wid & 1) * 32;
    #pragma unroll
    for (int mt = 0; mt < 2; mt++)
        #pragma unroll
        for (int j = 0; j < 4; j++) {
            #pragma unroll
            for (int half = 0; half < 2; half++) {
                const int row = i0 + wm + mt * 16 + (lane >> 2) + half * 8;
                const int col = j0 + wn + j * 8 + (lane & 3) * 2;
                const size_t idx = (size_t)row * 512 + col;
                float2 p = *(float2*)(g_Pf + idx);
                float v0 = 1.5f * p.x - 0.5f * acc[mt][j][half * 2];
                float v1 = 1.5f * p.y - 0.5f * acc[mt][j][half * 2 + 1];
                float2 pn; pn.x = v0; pn.y = v1;
                *(float2*)(g_Pf + idx) = pn;
                __nv_bfloat162 h = hi2(v0, v1);
                *(__nv_bfloat162*)(g_Phi + idx) = h;
                *(__nv_bfloat162*)(g_Plo + idx) = lo2(v0, v1, h);
            }
        }
}

// M = rot @ P * sqrt(1/tr); writes fp32 M + splits
__global__ void __launch_bounds__(128) k_rotp_tc() {
    __shared__ char sm[2 * 18432];
    float acc[2][4][4];
    const int i0 = blockIdx.y * 64, j0 = blockIdx.x * 64;
    tc64(g_rhi, g_rlo, g_Phi, g_Plo, i0, j0, sm, acc);
    const float s = g_scal[1];
    const int lane = threadIdx.x & 31, wid = threadIdx.x >> 5;
    const int wm = (wid >> 1) * 32, wn = (wid & 1) * 32;
    #pragma unroll
    for (int mt = 0; mt < 2; mt++)
        #pragma unroll
        for (int j = 0; j < 4; j++) {
            #pragma unroll
            for (int half = 0; half < 2; half++) {
                const int row = i0 + wm + mt * 16 + (lane >> 2) + half * 8;
                const int col = j0 + wn + j * 8 + (lane & 3) * 2;
                const size_t idx = (size_t)row * 512 + col;
                float v0 = acc[mt][j][half * 2] * s;
                float v1 = acc[mt][j][half * 2 + 1] * s;
                float2 m2; m2.x = v0; m2.y = v1;
                *(float2*)(g_M + idx) = m2;
                __nv_bfloat162 h = hi2(v0, v1);
                *(__nv_bfloat162*)(g_Mhi + idx) = h;
                *(__nv_bfloat162*)(g_Mlo + idx) = lo2(v0, v1, h);
            }
        }
}

__global__ void k_bias() {
    const int i = blockIdx.x * 256 + threadIdx.x;
    float s = 0.f;
    #pragma unroll 8
    for (int c = 0; c < CH; c++) s += g_M[(size_t)i * CH + c] * g_mean[c];
    g_bias[i] = s;
}

// ===================== out = M@X - bias (fp32 X, split in-kernel) ==========
#define O_STG  36864
#define O_SMEM (2 * O_STG)

__global__ void __launch_bounds__(256) k_out_mma(const float* __restrict__ Xf,
                                                 float* __restrict__ out) {
    extern __shared__ char smem[];
    const int tid = threadIdx.x, wid = tid >> 5, lane = tid & 31;
    const int b = blockIdx.z;
    const int i0 = blockIdx.y * 128;
    const int s0 = blockIdx.x * 128;
    const int wm = (wid & 3) * 32, wn = (wid >> 2) * 64;
    const uint32_t sbase = smem_u32(smem);

    const int aRow = wm + ((lane >> 3) & 1) * 8 + (lane & 7);
    const int aCol = (lane >> 4) * 16;
    const int bKr  = ((lane >> 3) & 1) * 8 + (lane & 7);
    const int bGg  = (wn >> 3) + (lane >> 4);

    float acc[2][8][4];
    #pragma unroll
    for (int mt = 0; mt < 2; mt++)
        #pragma unroll
        for (int nt = 0; nt < 8; nt++)
            #pragma unroll
            for (int q = 0; q < 4; q++) acc[mt][nt][q] = 0.f;

    uint4 va[4];
    float4 fb[2][2];
    const size_t Xb = (size_t)b * CH * SP;

#define O_LD(kk) do { const int k0 = (kk) * 32;                              \
    const int arow = tid >> 1, ahf = tid & 1;                                \
    const __nv_bfloat16* pm = g_Mhi + (size_t)(i0 + arow) * CH + k0 + ahf*16;\
    va[0] = *(const uint4*)(pm);  va[1] = *(const uint4*)(pm + 8);           \
    const __nv_bfloat16* pl = g_Mlo + (size_t)(i0 + arow) * CH + k0 + ahf*16;\
    va[2] = *(const uint4*)(pl);  va[3] = *(const uint4*)(pl + 8);           \
    const int kr = tid >> 3;                                                 \
    _Pragma("unroll")                                                        \
    for (int e = 0; e < 2; e++) {                                            \
        const int sg = (tid & 7) * 2 + e;                                    \
        const int sc = s0 + sg * 8;                                          \
        if (sc + 7 < SP) {                                                   \
            const float* px = Xf + Xb + (size_t)(k0 + kr) * SP + sc;         \
            fb[e][0] = *(const float4*)px;                                   \
            fb[e][1] = *(const float4*)(px + 4);                             \
        } else {                                                             \
            fb[e][0] = make_float4(0,0,0,0);                                 \
            fb[e][1] = make_float4(0,0,0,0);                                 \
        }                                                                    \
    } } while (0)

#define O_ST(sg_) do { char* _s = smem + (sg_) * O_STG;                      \
    const int arow = tid >> 1, ahf = tid & 1;                                \
    const int offA = arow * 80 + ahf * 32;                                   \
    *(uint4*)(_s + offA)      = va[0];  *(uint4*)(_s + offA + 16) = va[1];   \
    *(uint4*)(_s + 10240 + offA)      = va[2];                               \
    *(uint4*)(_s + 10240 + offA + 16) = va[3];                               \
    const int kr = tid >> 3;                                                 \
    _Pragma("unroll")                                                        \
    for (int e = 0; e < 2; e++) {                                            \
        const int sg = (tid & 7) * 2 + e;                                    \
        uint4 h, l; split8(fb[e][0], fb[e][1], h, l);                        \
        const int offB = kr * 256 + ((sg ^ (kr & 7)) << 4);                  \
        *(uint4*)(_s + 20480 + offB) = h;                                    \
        *(uint4*)(_s + 28672 + offB) = l;                                    \
    } } while (0)

    O_LD(0); O_ST(0); __syncthreads();
    for (int kk = 0; kk < 16; kk++) {
        if (kk < 15) O_LD(kk + 1);
        const uint32_t sa = sbase + (kk & 1) * O_STG;
        #pragma unroll
        for (int k16 = 0; k16 < 2; k16++) {
            uint32_t ah[2][4], al[2][4], bh[4][4], bl[4][4];
            #pragma unroll
            for (int mt = 0; mt < 2; mt++) {
                const uint32_t ao = sa + (aRow + mt * 16) * 80 + k16 * 32 + aCol;
                ldsm4(ah[mt], ao);
                ldsm4(al[mt], ao + 10240);
            }
            const int kr = k16 * 16 + bKr;
            #pragma unroll
            for (int np = 0; np < 4; np++) {
                const uint32_t bo = sa + 20480 + kr * 256 +
                                    (((bGg + np * 2) ^ (kr & 7)) << 4);
                ldsm4t(bh[np], bo);
                ldsm4t(bl[np], bo + 8192);
            }
            #pragma unroll
            for (int mt = 0; mt < 2; mt++)
                #pragma unroll
                for (int np = 0; np < 4; np++) {
                    mma16816(acc[mt][np*2],   ah[mt], &bh[np][0]);
                    mma16816(acc[mt][np*2+1], ah[mt], &bh[np][2]);
                    mma16816(acc[mt][np*2],   ah[mt], &bl[np][0]);
                    mma16816(acc[mt][np*2+1], ah[mt], &bl[np][2]);
                    mma16816(acc[mt][np*2],   al[mt], &bh[np][0]);
                    mma16816(acc[mt][np*2+1], al[mt], &bh[np][2]);
                }
        }
        __syncthreads();
        if (kk < 15) { O_ST((kk + 1) & 1); __syncthreads(); }
    }
#undef O_LD
#undef O_ST

    const int g4 = lane >> 2, t2 = (lane & 3) * 2;
    float* Ob = out + Xb;
    #pragma unroll
    for (int mt = 0; mt < 2; mt++) {
        const int gi = i0 + wm + mt * 16 + g4;
        const float b0 = g_bias[gi], b1 = g_bias[gi + 8];
        #pragma unroll
        for (int nt = 0; nt < 8; nt++) {
            const int col = s0 + wn + nt * 8 + t2;
            if (col < SP) {
                float2 v0; v0.x = acc[mt][nt][0] - b0; v0.y = acc[mt][nt][1] - b0;
                float2 v1; v1.x = acc[mt][nt][2] - b1; v1.y = acc[mt][nt][3] - b1;
                *(float2*)(Ob + (size_t)gi * SP + col)       = v0;
                *(float2*)(Ob + (size_t)(gi + 8) * SP + col) = v1;
            }
        }
    }
}

// ===================== launch ==============================================
extern "C" void kernel_launch(void* const* d_in, const int* in_sizes, int n_in,
                              void* d_out, int out_size) {
    const float* X   = (const float*)d_in[0];
    const float* rot = (const float*)d_in[1];
    float* out = (float*)d_out;
    (void)in_sizes; (void)n_in; (void)out_size;

    cudaFuncSetAttribute(k_gram_mma, cudaFuncAttributeMaxDynamicSharedMemorySize, G_SMEM);
    cudaFuncSetAttribute(k_out_mma,  cudaFuncAttributeMaxDynamicSharedMemorySize, O_SMEM);

    k_mean_part<<<dim3(CH, NB), 256>>>(X);       // 1
    k_mean_final<<<2, 256>>>();                  // 2
    k_rs<<<342, 256>>>(rot, 0);                  // 3
    k_rs<<<342, 256>>>(rot, 1);                  // 4
    k_rs<<<342, 256>>>(rot, 2);                  // 5
    k_gram_mma<<<dim3(10, NB), 256, G_SMEM>>>(X);// 6  <- ncu profiles this
    k_sigma<<<1024, 256>>>();
    k_trace<<<1, 512>>>();
    k_prep<<<1024, 256>>>();

    for (int t = 0; t < 10; t++) {
        k_nsA<<<dim3(8, 8, 2), 128>>>();
        k_nsB<<<dim3(8, 8), 128>>>();
    }
    k_rotp_tc<<<dim3(8, 8), 128>>>();
    k_bias<<<2, 256>>>();

    k_out_mma<<<dim3(25, 4, NB), 256, O_SMEM>>>(X, out);
}

// round 11
// speedup vs baseline: 1.1901x; 1.1901x over previous
#include <cuda_runtime.h>
#include <cuda_bf16.h>
#include <math.h>
#include <stdint.h>

#define CH   512
#define SP   3136
#define NB   32
#define MTOT 100352
#define EPSV 1e-5f

typedef unsigned long long ull;

// ===================== PTX helpers =========================================
__device__ __forceinline__ ull ffma2(ull a, ull b, ull c) {
    ull d;
    asm("fma.rn.f32x2 %0, %1, %2, %3;" : "=l"(d) : "l"(a), "l"(b), "l"(c));
    return d;
}
__device__ __forceinline__ float2 u2f2(ull v) {
    float2 r;
    asm("mov.b64 {%0, %1}, %2;" : "=f"(r.x), "=f"(r.y) : "l"(v));
    return r;
}
__device__ __forceinline__ uint32_t smem_u32(const void* p) {
    uint32_t a;
    asm("{ .reg .u64 t; cvta.to.shared.u64 t, %1; cvt.u32.u64 %0, t; }"
        : "=r"(a) : "l"(p));
    return a;
}
__device__ __forceinline__ void ldsm4(uint32_t r[4], uint32_t a) {
    asm volatile("ldmatrix.sync.aligned.m8n8.x4.shared.b16 {%0,%1,%2,%3}, [%4];"
                 : "=r"(r[0]), "=r"(r[1]), "=r"(r[2]), "=r"(r[3]) : "r"(a));
}
__device__ __forceinline__ void ldsm4t(uint32_t r[4], uint32_t a) {
    asm volatile("ldmatrix.sync.aligned.m8n8.x4.trans.shared.b16 {%0,%1,%2,%3}, [%4];"
                 : "=r"(r[0]), "=r"(r[1]), "=r"(r[2]), "=r"(r[3]) : "r"(a));
}
__device__ __forceinline__ void mma16816(float c[4], const uint32_t a[4],
                                         const uint32_t b[2]) {
    asm volatile("mma.sync.aligned.m16n8k16.row.col.f32.bf16.bf16.f32 "
                 "{%0,%1,%2,%3}, {%4,%5,%6,%7}, {%8,%9}, {%0,%1,%2,%3};"
                 : "+f"(c[0]), "+f"(c[1]), "+f"(c[2]), "+f"(c[3])
                 : "r"(a[0]), "r"(a[1]), "r"(a[2]), "r"(a[3]),
                   "r"(b[0]), "r"(b[1]));
}

union U4BF { uint4 u; __nv_bfloat162 h[4]; };

__device__ __forceinline__ void split8(const float4 a, const float4 b,
                                       uint4& hi, uint4& lo) {
    float f[8] = {a.x, a.y, a.z, a.w, b.x, b.y, b.z, b.w};
    U4BF H, L;
    #pragma unroll
    for (int i = 0; i < 4; i++) {
        __nv_bfloat16 h0 = __float2bfloat16(f[2*i]);
        __nv_bfloat16 h1 = __float2bfloat16(f[2*i+1]);
        __nv_bfloat162 hh; hh.x = h0; hh.y = h1;
        __nv_bfloat162 ll;
        ll.x = __float2bfloat16(f[2*i]   - __bfloat162float(h0));
        ll.y = __float2bfloat16(f[2*i+1] - __bfloat162float(h1));
        H.h[i] = hh; L.h[i] = ll;
    }
    hi = H.u; lo = L.u;
}

// ===================== scratch globals =====================================
__device__ __align__(16) __nv_bfloat16 g_Mhi[CH * CH];
__device__ __align__(16) __nv_bfloat16 g_Mlo[CH * CH];
__device__ float g_meanpart[NB * CH];
__device__ float g_mean[CH];
__device__ __align__(16) float g_Gsl[(size_t)NB * CH * CH];
__device__ float g_Sigma[CH * CH];
__device__ float g_SigmaN[CH * CH];
__device__ float g_Pa[CH * CH];
__device__ float g_Pb[CH * CH];
__device__ float g_P2[CH * CH];
__device__ float g_PS[CH * CH];
__device__ float g_M[CH * CH];
__device__ float g_bias[CH];
__device__ float g_scal[2];

// ===================== mean =================================================
__global__ void k_mean_part(const float* __restrict__ X) {
    const int c = blockIdx.x, b = blockIdx.y;
    const float* p = X + ((size_t)b * CH + c) * SP;
    float s = 0.f;
    for (int i = threadIdx.x * 4; i < SP; i += 1024) {
        float4 v = *(const float4*)(p + i);
        s += (v.x + v.y) + (v.z + v.w);
    }
    __shared__ float red[256];
    red[threadIdx.x] = s;
    __syncthreads();
    for (int o = 128; o > 0; o >>= 1) {
        if (threadIdx.x < o) red[threadIdx.x] += red[threadIdx.x + o];
        __syncthreads();
    }
    if (threadIdx.x == 0) g_meanpart[b * CH + c] = red[0];
}

__global__ void k_mean_final() {
    const int c = blockIdx.x * 256 + threadIdx.x;
    float s = 0.f;
    #pragma unroll
    for (int b = 0; b < NB; b++) s += g_meanpart[b * CH + c];
    g_mean[c] = s * (1.0f / MTOT);
}

// ===================== Gram via mma.sync (fp32 in, split in-kernel) ========
#define G_STG  40960
#define G_SMEM (2 * G_STG)

__global__ void __launch_bounds__(256) k_gram_mma(const float* __restrict__ Xf) {
    extern __shared__ char smem[];
    const int tid = threadIdx.x, wid = tid >> 5, lane = tid & 31;
    const int pair = blockIdx.x, slice = blockIdx.y;
    const int PI[10] = {0,0,0,0,1,1,1,2,2,3};
    const int PJ[10] = {0,1,2,3,1,2,3,2,3,3};
    const int m0 = PI[pair] * 128, n0 = PJ[pair] * 128;
    const int wm = (wid & 3) * 32, wn = (wid >> 2) * 64;
    const uint32_t sbase = smem_u32(smem);

    const int aRow = wm + ((lane >> 3) & 1) * 8 + (lane & 7);
    const int aCol = (lane >> 4) * 16;
    const int bRow = wn + (lane >> 4) * 8 + (lane & 7);
    const int bCol = ((lane >> 3) & 1) * 16;

    float acc[2][8][4];
    #pragma unroll
    for (int mt = 0; mt < 2; mt++)
        #pragma unroll
        for (int nt = 0; nt < 8; nt++)
            #pragma unroll
            for (int q = 0; q < 4; q++) acc[mt][nt][q] = 0.f;

    float4 fa[2][2], fb[2][2];
    const size_t Bbase = (size_t)slice * CH * SP;

#define G_LD(kk) do {                                                        \
    const int kbase = (kk) * 32;                                             \
    _Pragma("unroll")                                                        \
    for (int e = 0; e < 2; e++) {                                            \
        const int seg = tid * 2 + e;                                         \
        const int r = seg >> 2, q = seg & 3;                                 \
        const float* pa = Xf + Bbase + (size_t)(m0 + r) * SP + kbase + q * 8;\
        fa[e][0] = *(const float4*)(pa);                                     \
        fa[e][1] = *(const float4*)(pa + 4);                                 \
        const float* pb = Xf + Bbase + (size_t)(n0 + r) * SP + kbase + q * 8;\
        fb[e][0] = *(const float4*)(pb);                                     \
        fb[e][1] = *(const float4*)(pb + 4);                                 \
    } } while (0)

#define G_ST(sg) do { char* _s = smem + (sg) * G_STG;                        \
    _Pragma("unroll")                                                        \
    for (int e = 0; e < 2; e++) {                                            \
        const int seg = tid * 2 + e;                                         \
        const int r = seg >> 2, q = seg & 3;                                 \
        uint4 h, l;                                                          \
        split8(fa[e][0], fa[e][1], h, l);                                    \
        *(uint4*)(_s + r * 80 + q * 16) = h;                                 \
        *(uint4*)(_s + 10240 + r * 80 + q * 16) = l;                         \
        split8(fb[e][0], fb[e][1], h, l);                                    \
        *(uint4*)(_s + 20480 + r * 80 + q * 16) = h;                         \
        *(uint4*)(_s + 30720 + r * 80 + q * 16) = l;                         \
    } } while (0)

    G_LD(0); G_ST(0); __syncthreads();
    for (int kk = 0; kk < 98; kk++) {
        if (kk < 97) G_LD(kk + 1);
        const uint32_t sa = sbase + (kk & 1) * G_STG;
        #pragma unroll
        for (int k16 = 0; k16 < 2; k16++) {
            const int kb = k16 * 32;
            uint32_t ah[2][4], al[2][4], bh[4][4], bl[4][4];
            #pragma unroll
            for (int mt = 0; mt < 2; mt++) {
                const uint32_t ao = sa + (aRow + mt * 16) * 80 + kb + aCol;
                ldsm4(ah[mt], ao);
                ldsm4(al[mt], ao + 10240);
            }
            #pragma unroll
            for (int np = 0; np < 4; np++) {
                const uint32_t bo = sa + 20480 + (bRow + np * 16) * 80 + kb + bCol;
                ldsm4(bh[np], bo);
                ldsm4(bl[np], bo + 10240);
            }
            #pragma unroll
            for (int mt = 0; mt < 2; mt++)
                #pragma unroll
                for (int np = 0; np < 4; np++) {
                    mma16816(acc[mt][np*2],   ah[mt], &bh[np][0]);
                    mma16816(acc[mt][np*2+1], ah[mt], &bh[np][2]);
                    mma16816(acc[mt][np*2],   ah[mt], &bl[np][0]);
                    mma16816(acc[mt][np*2+1], ah[mt], &bl[np][2]);
                    mma16816(acc[mt][np*2],   al[mt], &bh[np][0]);
                    mma16816(acc[mt][np*2+1], al[mt], &bh[np][2]);
                }
        }
        __syncthreads();
        if (kk < 97) { G_ST((kk + 1) & 1); __syncthreads(); }
    }
#undef G_LD
#undef G_ST

    float* dst = g_Gsl + (size_t)slice * CH * CH;
    const int g4 = lane >> 2, t2 = (lane & 3) * 2;
    #pragma unroll
    for (int mt = 0; mt < 2; mt++)
        #pragma unroll
        for (int nt = 0; nt < 8; nt++) {
            const int row = m0 + wm + mt * 16 + g4;
            const int col = n0 + wn + nt * 8 + t2;
            float2 v0; v0.x = acc[mt][nt][0]; v0.y = acc[mt][nt][1];
            float2 v1; v1.x = acc[mt][nt][2]; v1.y = acc[mt][nt][3];
            *(float2*)(dst + (size_t)row * CH + col)       = v0;
            *(float2*)(dst + (size_t)(row + 8) * CH + col) = v1;
        }
}

// ===================== Sigma / trace / prep =================================
__global__ void k_sigma() {
    const int idx = blockIdx.x * 256 + threadIdx.x;
    const int i = idx >> 9, j = idx & 511;
    const size_t off = ((i >> 7) <= (j >> 7)) ? ((size_t)i * CH + j)
                                              : ((size_t)j * CH + i);
    float s = 0.f;
    #pragma unroll 8
    for (int p = 0; p < NB; p++) s += g_Gsl[(size_t)p * CH * CH + off];
    float v = s * (1.0f / MTOT) - g_mean[i] * g_mean[j];
    if (i == j) v += EPSV;
    g_Sigma[idx] = v;
}

__global__ void k_trace() {
    __shared__ float red[512];
    const int t = threadIdx.x;
    red[t] = g_Sigma[t * (CH + 1)];
    __syncthreads();
    for (int o = 256; o > 0; o >>= 1) {
        if (t < o) red[t] += red[t + o];
        __syncthreads();
    }
    if (t == 0) {
        float inv = 1.0f / red[0];
        g_scal[0] = inv;
        g_scal[1] = sqrtf(inv);
    }
}

__global__ void k_prep() {
    const int idx = blockIdx.x * 256 + threadIdx.x;
    g_SigmaN[idx] = g_Sigma[idx] * g_scal[0];
    const int i = idx >> 9, j = idx & 511;
    g_Pa[idx] = (i == j) ? 1.0f : 0.0f;
}

// ===================== Newton-Schulz (SIMT f32x2, known-good) ===============
__device__ __forceinline__ void mm512_acc(const float* __restrict__ A,
                                          const float* __restrict__ B,
                                          int i0, int j0, ull acc[4][2]) {
    __shared__ float As[16][128];
    __shared__ float Bs[16][64];
    const int tid = threadIdx.x;
    const int tx = tid & 15, ty = tid >> 4;
    #pragma unroll
    for (int r = 0; r < 4; r++) { acc[r][0] = 0ull; acc[r][1] = 0ull; }
    const int lr = tid >> 2, lq = (tid & 3) * 4;
    const int kb = tid >> 4, jb = (tid & 15) * 4;
    for (int k0 = 0; k0 < 512; k0 += 16) {
        float4 av = *(const float4*)(A + (size_t)(i0 + lr) * 512 + k0 + lq);
        float4 bv = *(const float4*)(B + (size_t)(k0 + kb) * 512 + j0 + jb);
        __syncthreads();
        As[lq + 0][2 * lr] = av.x; As[lq + 0][2 * lr + 1] = av.x;
        As[lq + 1][2 * lr] = av.y; As[lq + 1][2 * lr + 1] = av.y;
        As[lq + 2][2 * lr] = av.z; As[lq + 2][2 * lr + 1] = av.z;
        As[lq + 3][2 * lr] = av.w; As[lq + 3][2 * lr + 1] = av.w;
        *(float4*)&Bs[kb][jb] = bv;
        __syncthreads();
        #pragma unroll
        for (int kk = 0; kk < 16; kk++) {
            const ull* ap = (const ull*)&As[kk][ty * 8];
            const ull* bp = (const ull*)&Bs[kk][tx * 4];
            ull a[4], bb[2];
            #pragma unroll
            for (int r = 0; r < 4; r++) a[r] = ap[r];
            bb[0] = bp[0]; bb[1] = bp[1];
            #pragma unroll
            for (int r = 0; r < 4; r++) {
                acc[r][0] = ffma2(a[r], bb[0], acc[r][0]);
                acc[r][1] = ffma2(a[r], bb[1], acc[r][1]);
            }
        }
    }
}

__global__ void __launch_bounds__(256) k_ns_dual(int pb) {
    const float* P  = pb ? g_Pb : g_Pa;
    const float* Bm = blockIdx.z ? g_SigmaN : P;
    float*       Cm = blockIdx.z ? g_PS : g_P2;
    const int i0 = blockIdx.y * 64, j0 = blockIdx.x * 64;
    ull acc[4][2];
    mm512_acc(P, Bm, i0, j0, acc);
    const int tx = threadIdx.x & 15, ty = threadIdx.x >> 4;
    #pragma unroll
    for (int r = 0; r < 4; r++) {
        float* row = Cm + (size_t)(i0 + ty * 4 + r) * 512 + j0 + tx * 4;
        float2 v0 = u2f2(acc[r][0]), v1 = u2f2(acc[r][1]);
        row[0] = v0.x; row[1] = v0.y; row[2] = v1.x; row[3] = v1.y;
    }
}

__global__ void __launch_bounds__(256) k_ns_combine(int pb) {
    const float* Pc = pb ? g_Pb : g_Pa;
    float*       Pn = pb ? g_Pa : g_Pb;
    const int i0 = blockIdx.y * 64, j0 = blockIdx.x * 64;
    ull acc[4][2];
    mm512_acc(g_P2, g_PS, i0, j0, acc);
    const int tx = threadIdx.x & 15, ty = threadIdx.x >> 4;
    #pragma unroll
    for (int r = 0; r < 4; r++) {
        const size_t base = (size_t)(i0 + ty * 4 + r) * 512 + j0 + tx * 4;
        float2 v0 = u2f2(acc[r][0]), v1 = u2f2(acc[r][1]);
        Pn[base + 0] = 1.5f * Pc[base + 0] - 0.5f * v0.x;
        Pn[base + 1] = 1.5f * Pc[base + 1] - 0.5f * v0.y;
        Pn[base + 2] = 1.5f * Pc[base + 2] - 0.5f * v1.x;
        Pn[base + 3] = 1.5f * Pc[base + 3] - 0.5f * v1.y;
    }
}

__global__ void __launch_bounds__(256) k_rotP(const float* __restrict__ rot, int pb) {
    const float* Pf = pb ? g_Pb : g_Pa;
    const int i0 = blockIdx.y * 64, j0 = blockIdx.x * 64;
    ull acc[4][2];
    mm512_acc(rot, Pf, i0, j0, acc);
    const float s = g_scal[1];
    const int tx = threadIdx.x & 15, ty = threadIdx.x >> 4;
    #pragma unroll
    for (int r = 0; r < 4; r++) {
        float* row = g_M + (size_t)(i0 + ty * 4 + r) * 512 + j0 + tx * 4;
        float2 v0 = u2f2(acc[r][0]), v1 = u2f2(acc[r][1]);
        row[0] = v0.x * s; row[1] = v0.y * s; row[2] = v1.x * s; row[3] = v1.y * s;
    }
}

__global__ void k_Msplit() {
    const int idx = blockIdx.x * 256 + threadIdx.x;
    float v = g_M[idx];
    __nv_bfloat16 h = __float2bfloat16(v);
    g_Mhi[idx] = h;
    g_Mlo[idx] = __float2bfloat16(v - __bfloat162float(h));
}

__global__ void k_bias() {
    const int i = blockIdx.x * 256 + threadIdx.x;
    float s = 0.f;
    #pragma unroll 8
    for (int c = 0; c < CH; c++) s += g_M[(size_t)i * CH + c] * g_mean[c];
    g_bias[i] = s;
}

// ===================== out = M@X - bias (fp32 X, split in-kernel) ==========
#define O_STG  36864
#define O_SMEM (2 * O_STG)

__global__ void __launch_bounds__(256) k_out_mma(const float* __restrict__ Xf,
                                                 float* __restrict__ out) {
    extern __shared__ char smem[];
    const int tid = threadIdx.x, wid = tid >> 5, lane = tid & 31;
    const int b = blockIdx.z;
    const int i0 = blockIdx.y * 128;
    const int s0 = blockIdx.x * 128;
    const int wm = (wid & 3) * 32, wn = (wid >> 2) * 64;
    const uint32_t sbase = smem_u32(smem);

    const int aRow = wm + ((lane >> 3) & 1) * 8 + (lane & 7);
    const int aCol = (lane >> 4) * 16;
    const int bKr  = ((lane >> 3) & 1) * 8 + (lane & 7);
    const int bGg  = (wn >> 3) + (lane >> 4);

    float acc[2][8][4];
    #pragma unroll
    for (int mt = 0; mt < 2; mt++)
        #pragma unroll
        for (int nt = 0; nt < 8; nt++)
            #pragma unroll
            for (int q = 0; q < 4; q++) acc[mt][nt][q] = 0.f;

    uint4 va[4];
    float4 fb[2][2];
    const size_t Xb = (size_t)b * CH * SP;

#define O_LD(kk) do { const int k0 = (kk) * 32;                              \
    const int arow = tid >> 1, ahf = tid & 1;                                \
    const __nv_bfloat16* pm = g_Mhi + (size_t)(i0 + arow) * CH + k0 + ahf*16;\
    va[0] = *(const uint4*)(pm);  va[1] = *(const uint4*)(pm + 8);           \
    const __nv_bfloat16* pl = g_Mlo + (size_t)(i0 + arow) * CH + k0 + ahf*16;\
    va[2] = *(const uint4*)(pl);  va[3] = *(const uint4*)(pl + 8);           \
    const int kr = tid >> 3;                                                 \
    _Pragma("unroll")                                                        \
    for (int e = 0; e < 2; e++) {                                            \
        const int sg = (tid & 7) * 2 + e;                                    \
        const int sc = s0 + sg * 8;                                          \
        if (sc + 7 < SP) {                                                   \
            const float* px = Xf + Xb + (size_t)(k0 + kr) * SP + sc;         \
            fb[e][0] = *(const float4*)px;                                   \
            fb[e][1] = *(const float4*)(px + 4);                             \
        } else {                                                             \
            fb[e][0] = make_float4(0,0,0,0);                                 \
            fb[e][1] = make_float4(0,0,0,0);                                 \
        }                                                                    \
    } } while (0)

#define O_ST(sg_) do { char* _s = smem + (sg_) * O_STG;                      \
    const int arow = tid >> 1, ahf = tid & 1;                                \
    const int offA = arow * 80 + ahf * 32;                                   \
    *(uint4*)(_s + offA)      = va[0];  *(uint4*)(_s + offA + 16) = va[1];   \
    *(uint4*)(_s + 10240 + offA)      = va[2];                               \
    *(uint4*)(_s + 10240 + offA + 16) = va[3];                               \
    const int kr = tid >> 3;                                                 \
    _Pragma("unroll")                                                        \
    for (int e = 0; e < 2; e++) {                                            \
        const int sg = (tid & 7) * 2 + e;                                    \
        uint4 h, l; split8(fb[e][0], fb[e][1], h, l);                        \
        const int offB = kr * 256 + ((sg ^ (kr & 7)) << 4);                  \
        *(uint4*)(_s + 20480 + offB) = h;                                    \
        *(uint4*)(_s + 28672 + offB) = l;                                    \
    } } while (0)

    O_LD(0); O_ST(0); __syncthreads();
    for (int kk = 0; kk < 16; kk++) {
        if (kk < 15) O_LD(kk + 1);
        const uint32_t sa = sbase + (kk & 1) * O_STG;
        #pragma unroll
        for (int k16 = 0; k16 < 2; k16++) {
            uint32_t ah[2][4], al[2][4], bh[4][4], bl[4][4];
            #pragma unroll
            for (int mt = 0; mt < 2; mt++) {
                const uint32_t ao = sa + (aRow + mt * 16) * 80 + k16 * 32 + aCol;
                ldsm4(ah[mt], ao);
                ldsm4(al[mt], ao + 10240);
            }
            const int kr = k16 * 16 + bKr;
            #pragma unroll
            for (int np = 0; np < 4; np++) {
                const uint32_t bo = sa + 20480 + kr * 256 +
                                    (((bGg + np * 2) ^ (kr & 7)) << 4);
                ldsm4t(bh[np], bo);
                ldsm4t(bl[np], bo + 8192);
            }
            #pragma unroll
            for (int mt = 0; mt < 2; mt++)
                #pragma unroll
                for (int np = 0; np < 4; np++) {
                    mma16816(acc[mt][np*2],   ah[mt], &bh[np][0]);
                    mma16816(acc[mt][np*2+1], ah[mt], &bh[np][2]);
                    mma16816(acc[mt][np*2],   ah[mt], &bl[np][0]);
                    mma16816(acc[mt][np*2+1], ah[mt], &bl[np][2]);
                    mma16816(acc[mt][np*2],   al[mt], &bh[np][0]);
                    mma16816(acc[mt][np*2+1], al[mt], &bh[np][2]);
                }
        }
        __syncthreads();
        if (kk < 15) { O_ST((kk + 1) & 1); __syncthreads(); }
    }
#undef O_LD
#undef O_ST

    const int g4 = lane >> 2, t2 = (lane & 3) * 2;
    float* Ob = out + Xb;
    #pragma unroll
    for (int mt = 0; mt < 2; mt++) {
        const int gi = i0 + wm + mt * 16 + g4;
        const float b0 = g_bias[gi], b1 = g_bias[gi + 8];
        #pragma unroll
        for (int nt = 0; nt < 8; nt++) {
            const int col = s0 + wn + nt * 8 + t2;
            if (col < SP) {
                float2 v0; v0.x = acc[mt][nt][0] - b0; v0.y = acc[mt][nt][1] - b0;
                float2 v1; v1.x = acc[mt][nt][2] - b1; v1.y = acc[mt][nt][3] - b1;
                *(float2*)(Ob + (size_t)gi * SP + col)       = v0;
                *(float2*)(Ob + (size_t)(gi + 8) * SP + col) = v1;
            }
        }
    }
}

// ===================== launch ==============================================
extern "C" void kernel_launch(void* const* d_in, const int* in_sizes, int n_in,
                              void* d_out, int out_size) {
    const float* X   = (const float*)d_in[0];
    const float* rot = (const float*)d_in[1];
    float* out = (float*)d_out;
    (void)in_sizes; (void)n_in; (void)out_size;

    cudaFuncSetAttribute(k_gram_mma, cudaFuncAttributeMaxDynamicSharedMemorySize, G_SMEM);
    cudaFuncSetAttribute(k_out_mma,  cudaFuncAttributeMaxDynamicSharedMemorySize, O_SMEM);

    k_mean_part<<<dim3(CH, NB), 256>>>(X);        // 1
    k_mean_final<<<2, 256>>>();                   // 2
    k_mean_final<<<2, 256>>>();                   // 3 (slot pad; idempotent)
    k_gram_mma<<<dim3(10, NB), 256, G_SMEM>>>(X); // 4 <- ncu slot
    k_sigma<<<1024, 256>>>();
    k_trace<<<1, 512>>>();
    k_prep<<<1024, 256>>>();

    for (int t = 0; t < 10; t++) {
        const int pb = t & 1;
        k_ns_dual<<<dim3(8, 8, 2), 256>>>(pb);
        k_ns_combine<<<dim3(8, 8), 256>>>(pb);
    }
    k_rotP<<<dim3(8, 8), 256>>>(rot, 0);
    k_Msplit<<<1024, 256>>>();
    k_bias<<<2, 256>>>();

    k_out_mma<<<dim3(25, 4, NB), 256, O_SMEM>>>(X, out);
}

// round 12
// speedup vs baseline: 1.3960x; 1.1730x over previous
#include <cuda_runtime.h>
#include <cuda_bf16.h>
#include <math.h>
#include <stdint.h>

#define CH   512
#define SP   3136
#define NB   32
#define MTOT 100352
#define EPSV 1e-5f

typedef unsigned long long ull;

// ===================== PTX helpers =========================================
__device__ __forceinline__ ull ffma2(ull a, ull b, ull c) {
    ull d;
    asm("fma.rn.f32x2 %0, %1, %2, %3;" : "=l"(d) : "l"(a), "l"(b), "l"(c));
    return d;
}
__device__ __forceinline__ float2 u2f2(ull v) {
    float2 r;
    asm("mov.b64 {%0, %1}, %2;" : "=f"(r.x), "=f"(r.y) : "l"(v));
    return r;
}
__device__ __forceinline__ uint32_t smem_u32(const void* p) {
    uint32_t a;
    asm("{ .reg .u64 t; cvta.to.shared.u64 t, %1; cvt.u32.u64 %0, t; }"
        : "=r"(a) : "l"(p));
    return a;
}
__device__ __forceinline__ void ldsm4(uint32_t r[4], uint32_t a) {
    asm volatile("ldmatrix.sync.aligned.m8n8.x4.shared.b16 {%0,%1,%2,%3}, [%4];"
                 : "=r"(r[0]), "=r"(r[1]), "=r"(r[2]), "=r"(r[3]) : "r"(a));
}
__device__ __forceinline__ void ldsm4t(uint32_t r[4], uint32_t a) {
    asm volatile("ldmatrix.sync.aligned.m8n8.x4.trans.shared.b16 {%0,%1,%2,%3}, [%4];"
                 : "=r"(r[0]), "=r"(r[1]), "=r"(r[2]), "=r"(r[3]) : "r"(a));
}
__device__ __forceinline__ void mma16816(float c[4], const uint32_t a[4],
                                         const uint32_t b[2]) {
    asm volatile("mma.sync.aligned.m16n8k16.row.col.f32.bf16.bf16.f32 "
                 "{%0,%1,%2,%3}, {%4,%5,%6,%7}, {%8,%9}, {%0,%1,%2,%3};"
                 : "+f"(c[0]), "+f"(c[1]), "+f"(c[2]), "+f"(c[3])
                 : "r"(a[0]), "r"(a[1]), "r"(a[2]), "r"(a[3]),
                   "r"(b[0]), "r"(b[1]));
}
__device__ __forceinline__ void cpa16(uint32_t smem, const void* gmem) {
    asm volatile("cp.async.cg.shared.global [%0], [%1], 16;"
                 :: "r"(smem), "l"(gmem));
}
__device__ __forceinline__ void cpa16z(uint32_t smem, const void* gmem, int nb) {
    asm volatile("cp.async.cg.shared.global [%0], [%1], 16, %2;"
                 :: "r"(smem), "l"(gmem), "r"(nb));
}
#define CPA_COMMIT() asm volatile("cp.async.commit_group;" ::: "memory")
#define CPA_WAIT1()  asm volatile("cp.async.wait_group 1;" ::: "memory")
#define CPA_WAIT0()  asm volatile("cp.async.wait_group 0;" ::: "memory")

// ===================== scratch globals =====================================
__device__ __align__(16) __nv_bfloat16 g_Xhi[(size_t)NB * CH * SP];
__device__ __align__(16) __nv_bfloat16 g_Xlo[(size_t)NB * CH * SP];
__device__ __align__(16) __nv_bfloat16 g_Mhi[CH * CH];
__device__ __align__(16) __nv_bfloat16 g_Mlo[CH * CH];
__device__ float g_meanpart[NB * CH];
__device__ float g_mean[CH];
__device__ __align__(16) float g_Gsl[(size_t)NB * CH * CH];
__device__ float g_Sigma[CH * CH];
__device__ float g_SigmaN[CH * CH];
__device__ float g_Pa[CH * CH];
__device__ float g_Pb[CH * CH];
__device__ float g_P2[CH * CH];
__device__ float g_PS[CH * CH];
__device__ float g_M[CH * CH];
__device__ float g_bias[CH];
__device__ float g_scal[2];

// ===================== convert + fused mean partials =======================
__global__ void __launch_bounds__(256) k_convert(const float* __restrict__ X) {
    const int c = blockIdx.x, b = blockIdx.y;
    const size_t base = ((size_t)b * CH + c) * SP;
    const float* src = X + base;
    float s = 0.f;
    for (int i = threadIdx.x * 4; i < SP; i += 1024) {
        float4 v = *(const float4*)(src + i);
        s += (v.x + v.y) + (v.z + v.w);
        __nv_bfloat16 h0 = __float2bfloat16(v.x), h1 = __float2bfloat16(v.y);
        __nv_bfloat16 h2 = __float2bfloat16(v.z), h3 = __float2bfloat16(v.w);
        __nv_bfloat162 hh0; hh0.x = h0; hh0.y = h1;
        __nv_bfloat162 hh1; hh1.x = h2; hh1.y = h3;
        __nv_bfloat162 ll0, ll1;
        ll0.x = __float2bfloat16(v.x - __bfloat162float(h0));
        ll0.y = __float2bfloat16(v.y - __bfloat162float(h1));
        ll1.x = __float2bfloat16(v.z - __bfloat162float(h2));
        ll1.y = __float2bfloat16(v.w - __bfloat162float(h3));
        *(__nv_bfloat162*)(g_Xhi + base + i)     = hh0;
        *(__nv_bfloat162*)(g_Xhi + base + i + 2) = hh1;
        *(__nv_bfloat162*)(g_Xlo + base + i)     = ll0;
        *(__nv_bfloat162*)(g_Xlo + base + i + 2) = ll1;
    }
    __shared__ float red[256];
    red[threadIdx.x] = s;
    __syncthreads();
    for (int o = 128; o > 0; o >>= 1) {
        if (threadIdx.x < o) red[threadIdx.x] += red[threadIdx.x + o];
        __syncthreads();
    }
    if (threadIdx.x == 0) g_meanpart[b * CH + c] = red[0];
}

__global__ void k_mean_final() {
    const int c = blockIdx.x * 256 + threadIdx.x;
    float s = 0.f;
    #pragma unroll
    for (int b = 0; b < NB; b++) s += g_meanpart[b * CH + c];
    g_mean[c] = s * (1.0f / MTOT);
}

// ===================== Gram via mma.sync + cp.async ========================
// stage: Ahi[128x80B] Alo Bhi Blo = 40960; x2 stages = 80K
#define G_STG  40960
#define G_SMEM (2 * G_STG)

__global__ void __launch_bounds__(256, 2) k_gram_mma() {
    extern __shared__ char smem[];
    const int tid = threadIdx.x, wid = tid >> 5, lane = tid & 31;
    const int pair = blockIdx.x, slice = blockIdx.y;
    const int PI[10] = {0,0,0,0,1,1,1,2,2,3};
    const int PJ[10] = {0,1,2,3,1,2,3,2,3,3};
    const int m0 = PI[pair] * 128, n0 = PJ[pair] * 128;
    const int wm = (wid & 3) * 32, wn = (wid >> 2) * 64;
    const uint32_t sbase = smem_u32(smem);
    const size_t Bbase = (size_t)slice * CH * SP;

    const int aRow = wm + ((lane >> 3) & 1) * 8 + (lane & 7);
    const int aCol = (lane >> 4) * 16;
    const int bRow = wn + (lane >> 4) * 8 + (lane & 7);
    const int bCol = ((lane >> 3) & 1) * 16;

    float acc[2][8][4];
    #pragma unroll
    for (int mt = 0; mt < 2; mt++)
        #pragma unroll
        for (int nt = 0; nt < 8; nt++)
            #pragma unroll
            for (int q = 0; q < 4; q++) acc[mt][nt][q] = 0.f;

    // async load of one K=32 chunk into stage sg: 2048 16B segments, 8/thread
#define G_LD(kk, sg) do {                                                    \
    const uint32_t sb0 = sbase + (sg) * G_STG;                               \
    const int kb = (kk) * 32;                                                \
    _Pragma("unroll")                                                        \
    for (int e = 0; e < 8; e++) {                                            \
        const int chunk = e * 256 + tid;                                     \
        const int mat = chunk >> 9;                                          \
        const int idx = chunk & 511;                                         \
        const int row = idx >> 2, q = idx & 3;                               \
        const __nv_bfloat16* src = ((mat & 1) ? g_Xlo : g_Xhi) + Bbase       \
            + (size_t)(((mat >> 1) ? n0 : m0) + row) * SP + kb + q * 8;      \
        cpa16(sb0 + mat * 10240 + row * 80 + q * 16, src);                   \
    }                                                                        \
    CPA_COMMIT();                                                            \
} while (0)

    G_LD(0, 0);
    for (int kk = 0; kk < 98; kk++) {
        if (kk < 97) { G_LD(kk + 1, (kk + 1) & 1); CPA_WAIT1(); }
        else CPA_WAIT0();
        __syncthreads();
        const uint32_t sa = sbase + (kk & 1) * G_STG;
        #pragma unroll
        for (int k16 = 0; k16 < 2; k16++) {
            const int kb = k16 * 32;
            uint32_t ah[2][4], al[2][4], bh[4][4], bl[4][4];
            #pragma unroll
            for (int mt = 0; mt < 2; mt++) {
                const uint32_t ao = sa + (aRow + mt * 16) * 80 + kb + aCol;
                ldsm4(ah[mt], ao);
                ldsm4(al[mt], ao + 10240);
            }
            #pragma unroll
            for (int np = 0; np < 4; np++) {
                const uint32_t bo = sa + 20480 + (bRow + np * 16) * 80 + kb + bCol;
                ldsm4(bh[np], bo);
                ldsm4(bl[np], bo + 10240);
            }
            #pragma unroll
            for (int mt = 0; mt < 2; mt++)
                #pragma unroll
                for (int np = 0; np < 4; np++) {
                    mma16816(acc[mt][np*2],   ah[mt], &bh[np][0]);
                    mma16816(acc[mt][np*2+1], ah[mt], &bh[np][2]);
                    mma16816(acc[mt][np*2],   ah[mt], &bl[np][0]);
                    mma16816(acc[mt][np*2+1], ah[mt], &bl[np][2]);
                    mma16816(acc[mt][np*2],   al[mt], &bh[np][0]);
                    mma16816(acc[mt][np*2+1], al[mt], &bh[np][2]);
                }
        }
        __syncthreads();
    }
#undef G_LD

    float* dst = g_Gsl + (size_t)slice * CH * CH;
    const int g4 = lane >> 2, t2 = (lane & 3) * 2;
    #pragma unroll
    for (int mt = 0; mt < 2; mt++)
        #pragma unroll
        for (int nt = 0; nt < 8; nt++) {
            const int row = m0 + wm + mt * 16 + g4;
            const int col = n0 + wn + nt * 8 + t2;
            float2 v0; v0.x = acc[mt][nt][0]; v0.y = acc[mt][nt][1];
            float2 v1; v1.x = acc[mt][nt][2]; v1.y = acc[mt][nt][3];
            *(float2*)(dst + (size_t)row * CH + col)       = v0;
            *(float2*)(dst + (size_t)(row + 8) * CH + col) = v1;
        }
}

// ===================== Sigma / trace / prep =================================
__global__ void k_sigma() {
    const int idx = blockIdx.x * 256 + threadIdx.x;
    const int i = idx >> 9, j = idx & 511;
    const size_t off = ((i >> 7) <= (j >> 7)) ? ((size_t)i * CH + j)
                                              : ((size_t)j * CH + i);
    float s = 0.f;
    #pragma unroll 8
    for (int p = 0; p < NB; p++) s += g_Gsl[(size_t)p * CH * CH + off];
    float v = s * (1.0f / MTOT) - g_mean[i] * g_mean[j];
    if (i == j) v += EPSV;
    g_Sigma[idx] = v;
}

__global__ void k_trace() {
    __shared__ float red[512];
    const int t = threadIdx.x;
    red[t] = g_Sigma[t * (CH + 1)];
    __syncthreads();
    for (int o = 256; o > 0; o >>= 1) {
        if (t < o) red[t] += red[t + o];
        __syncthreads();
    }
    if (t == 0) {
        float inv = 1.0f / red[0];
        g_scal[0] = inv;
        g_scal[1] = sqrtf(inv);
    }
}

__global__ void k_prep() {
    const int idx = blockIdx.x * 256 + threadIdx.x;
    g_SigmaN[idx] = g_Sigma[idx] * g_scal[0];
    const int i = idx >> 9, j = idx & 511;
    g_Pa[idx] = (i == j) ? 1.0f : 0.0f;
}

// ===================== Newton-Schulz (SIMT f32x2, known-good) ===============
__device__ __forceinline__ void mm512_acc(const float* __restrict__ A,
                                          const float* __restrict__ B,
                                          int i0, int j0, ull acc[4][2]) {
    __shared__ float As[16][128];
    __shared__ float Bs[16][64];
    const int tid = threadIdx.x;
    const int tx = tid & 15, ty = tid >> 4;
    #pragma unroll
    for (int r = 0; r < 4; r++) { acc[r][0] = 0ull; acc[r][1] = 0ull; }
    const int lr = tid >> 2, lq = (tid & 3) * 4;
    const int kb = tid >> 4, jb = (tid & 15) * 4;
    for (int k0 = 0; k0 < 512; k0 += 16) {
        float4 av = *(const float4*)(A + (size_t)(i0 + lr) * 512 + k0 + lq);
        float4 bv = *(const float4*)(B + (size_t)(k0 + kb) * 512 + j0 + jb);
        __syncthreads();
        As[lq + 0][2 * lr] = av.x; As[lq + 0][2 * lr + 1] = av.x;
        As[lq + 1][2 * lr] = av.y; As[lq + 1][2 * lr + 1] = av.y;
        As[lq + 2][2 * lr] = av.z; As[lq + 2][2 * lr + 1] = av.z;
        As[lq + 3][2 * lr] = av.w; As[lq + 3][2 * lr + 1] = av.w;
        *(float4*)&Bs[kb][jb] = bv;
        __syncthreads();
        #pragma unroll
        for (int kk = 0; kk < 16; kk++) {
            const ull* ap = (const ull*)&As[kk][ty * 8];
            const ull* bp = (const ull*)&Bs[kk][tx * 4];
            ull a[4], bb[2];
            #pragma unroll
            for (int r = 0; r < 4; r++) a[r] = ap[r];
            bb[0] = bp[0]; bb[1] = bp[1];
            #pragma unroll
            for (int r = 0; r < 4; r++) {
                acc[r][0] = ffma2(a[r], bb[0], acc[r][0]);
                acc[r][1] = ffma2(a[r], bb[1], acc[r][1]);
            }
        }
    }
}

__global__ void __launch_bounds__(256) k_ns_dual(int pb) {
    const float* P  = pb ? g_Pb : g_Pa;
    const float* Bm = blockIdx.z ? g_SigmaN : P;
    float*       Cm = blockIdx.z ? g_PS : g_P2;
    const int i0 = blockIdx.y * 64, j0 = blockIdx.x * 64;
    ull acc[4][2];
    mm512_acc(P, Bm, i0, j0, acc);
    const int tx = threadIdx.x & 15, ty = threadIdx.x >> 4;
    #pragma unroll
    for (int r = 0; r < 4; r++) {
        float* row = Cm + (size_t)(i0 + ty * 4 + r) * 512 + j0 + tx * 4;
        float2 v0 = u2f2(acc[r][0]), v1 = u2f2(acc[r][1]);
        row[0] = v0.x; row[1] = v0.y; row[2] = v1.x; row[3] = v1.y;
    }
}

__global__ void __launch_bounds__(256) k_ns_combine(int pb) {
    const float* Pc = pb ? g_Pb : g_Pa;
    float*       Pn = pb ? g_Pa : g_Pb;
    const int i0 = blockIdx.y * 64, j0 = blockIdx.x * 64;
    ull acc[4][2];
    mm512_acc(g_P2, g_PS, i0, j0, acc);
    const int tx = threadIdx.x & 15, ty = threadIdx.x >> 4;
    #pragma unroll
    for (int r = 0; r < 4; r++) {
        const size_t base = (size_t)(i0 + ty * 4 + r) * 512 + j0 + tx * 4;
        float2 v0 = u2f2(acc[r][0]), v1 = u2f2(acc[r][1]);
        Pn[base + 0] = 1.5f * Pc[base + 0] - 0.5f * v0.x;
        Pn[base + 1] = 1.5f * Pc[base + 1] - 0.5f * v0.y;
        Pn[base + 2] = 1.5f * Pc[base + 2] - 0.5f * v1.x;
        Pn[base + 3] = 1.5f * Pc[base + 3] - 0.5f * v1.y;
    }
}

__global__ void __launch_bounds__(256) k_rotP(const float* __restrict__ rot, int pb) {
    const float* Pf = pb ? g_Pb : g_Pa;
    const int i0 = blockIdx.y * 64, j0 = blockIdx.x * 64;
    ull acc[4][2];
    mm512_acc(rot, Pf, i0, j0, acc);
    const float s = g_scal[1];
    const int tx = threadIdx.x & 15, ty = threadIdx.x >> 4;
    #pragma unroll
    for (int r = 0; r < 4; r++) {
        float* row = g_M + (size_t)(i0 + ty * 4 + r) * 512 + j0 + tx * 4;
        float2 v0 = u2f2(acc[r][0]), v1 = u2f2(acc[r][1]);
        row[0] = v0.x * s; row[1] = v0.y * s; row[2] = v1.x * s; row[3] = v1.y * s;
    }
}

__global__ void k_Msplit() {
    const int idx = blockIdx.x * 256 + threadIdx.x;
    float v = g_M[idx];
    __nv_bfloat16 h = __float2bfloat16(v);
    g_Mhi[idx] = h;
    g_Mlo[idx] = __float2bfloat16(v - __bfloat162float(h));
}

__global__ void k_bias() {
    const int i = blockIdx.x * 256 + threadIdx.x;
    float s = 0.f;
    #pragma unroll 8
    for (int c = 0; c < CH; c++) s += g_M[(size_t)i * CH + c] * g_mean[c];
    g_bias[i] = s;
}

// ===================== out = M@X - bias via mma.sync + cp.async ============
// stage: Ahi[128x80B]=10240 Alo=10240 Bhi[32x256B]=8192 Blo=8192 => 36864
#define O_STG  36864
#define O_SMEM (2 * O_STG)

__global__ void __launch_bounds__(256, 2) k_out_mma(float* __restrict__ out) {
    extern __shared__ char smem[];
    const int tid = threadIdx.x, wid = tid >> 5, lane = tid & 31;
    const int b = blockIdx.z;
    const int i0 = blockIdx.y * 128;
    const int s0 = blockIdx.x * 128;
    const int wm = (wid & 3) * 32, wn = (wid >> 2) * 64;
    const uint32_t sbase = smem_u32(smem);
    const size_t Xb = (size_t)b * CH * SP;

    const int aRow = wm + ((lane >> 3) & 1) * 8 + (lane & 7);
    const int aCol = (lane >> 4) * 16;
    const int bKr  = ((lane >> 3) & 1) * 8 + (lane & 7);
    const int bGg  = (wn >> 3) + (lane >> 4);

    float acc[2][8][4];
    #pragma unroll
    for (int mt = 0; mt < 2; mt++)
        #pragma unroll
        for (int nt = 0; nt < 8; nt++)
            #pragma unroll
            for (int q = 0; q < 4; q++) acc[mt][nt][q] = 0.f;

    // 2048 chunks/stage: mat0 Ahi, mat1 Alo, mat2 Bhi, mat3 Blo; 8/thread
#define O_LD(kk, sg) do {                                                    \
    const uint32_t sb0 = sbase + (sg) * O_STG;                               \
    const int k0 = (kk) * 32;                                                \
    _Pragma("unroll")                                                        \
    for (int e = 0; e < 8; e++) {                                            \
        const int chunk = e * 256 + tid;                                     \
        const int mat = chunk >> 9;                                          \
        const int idx = chunk & 511;                                         \
        if (mat < 2) {                                                       \
            const int row = idx >> 2, q = idx & 3;                           \
            const __nv_bfloat16* src = (mat ? g_Mlo : g_Mhi)                 \
                + (size_t)(i0 + row) * CH + k0 + q * 8;                      \
            cpa16(sb0 + mat * 10240 + row * 80 + q * 16, src);               \
        } else {                                                             \
            const int kr = idx >> 4, sg2 = idx & 15;                         \
            const int sc = s0 + sg2 * 8;                                     \
            const int nb = (sc + 8 <= SP) ? 16 : 0;                          \
            const __nv_bfloat16* src = ((mat & 1) ? g_Xlo : g_Xhi) + Xb      \
                + (size_t)(k0 + kr) * SP + ((sc + 8 <= SP) ? sc : 0);        \
            cpa16z(sb0 + 20480 + (mat & 1) * 8192 + kr * 256                 \
                   + (((sg2) ^ (kr & 7)) << 4), src, nb);                    \
        }                                                                    \
    }                                                                        \
    CPA_COMMIT();                                                            \
} while (0)

    O_LD(0, 0);
    for (int kk = 0; kk < 16; kk++) {
        if (kk < 15) { O_LD(kk + 1, (kk + 1) & 1); CPA_WAIT1(); }
        else CPA_WAIT0();
        __syncthreads();
        const uint32_t sa = sbase + (kk & 1) * O_STG;
        #pragma unroll
        for (int k16 = 0; k16 < 2; k16++) {
            uint32_t ah[2][4], al[2][4], bh[4][4], bl[4][4];
            #pragma unroll
            for (int mt = 0; mt < 2; mt++) {
                const uint32_t ao = sa + (aRow + mt * 16) * 80 + k16 * 32 + aCol;
                ldsm4(ah[mt], ao);
                ldsm4(al[mt], ao + 10240);
            }
            const int kr = k16 * 16 + bKr;
            #pragma unroll
            for (int np = 0; np < 4; np++) {
                const uint32_t bo = sa + 20480 + kr * 256 +
                                    (((bGg + np * 2) ^ (kr & 7)) << 4);
                ldsm4t(bh[np], bo);
                ldsm4t(bl[np], bo + 8192);
            }
            #pragma unroll
            for (int mt = 0; mt < 2; mt++)
                #pragma unroll
                for (int np = 0; np < 4; np++) {
                    mma16816(acc[mt][np*2],   ah[mt], &bh[np][0]);
                    mma16816(acc[mt][np*2+1], ah[mt], &bh[np][2]);
                    mma16816(acc[mt][np*2],   ah[mt], &bl[np][0]);
                    mma16816(acc[mt][np*2+1], ah[mt], &bl[np][2]);
                    mma16816(acc[mt][np*2],   al[mt], &bh[np][0]);
                    mma16816(acc[mt][np*2+1], al[mt], &bh[np][2]);
                }
        }
        __syncthreads();
    }
#undef O_LD

    const int g4 = lane >> 2, t2 = (lane & 3) * 2;
    float* Ob = out + Xb;
    #pragma unroll
    for (int mt = 0; mt < 2; mt++) {
        const int gi = i0 + wm + mt * 16 + g4;
        const float b0 = g_bias[gi], b1 = g_bias[gi + 8];
        #pragma unroll
        for (int nt = 0; nt < 8; nt++) {
            const int col = s0 + wn + nt * 8 + t2;
            if (col < SP) {
                float2 v0; v0.x = acc[mt][nt][0] - b0; v0.y = acc[mt][nt][1] - b0;
                float2 v1; v1.x = acc[mt][nt][2] - b1; v1.y = acc[mt][nt][3] - b1;
                *(float2*)(Ob + (size_t)gi * SP + col)       = v0;
                *(float2*)(Ob + (size_t)(gi + 8) * SP + col) = v1;
            }
        }
    }
}

// ===================== launch ==============================================
extern "C" void kernel_launch(void* const* d_in, const int* in_sizes, int n_in,
                              void* d_out, int out_size) {
    const float* X   = (const float*)d_in[0];
    const float* rot = (const float*)d_in[1];
    float* out = (float*)d_out;
    (void)in_sizes; (void)n_in; (void)out_size;

    cudaFuncSetAttribute(k_gram_mma, cudaFuncAttributeMaxDynamicSharedMemorySize, G_SMEM);
    cudaFuncSetAttribute(k_out_mma,  cudaFuncAttributeMaxDynamicSharedMemorySize, O_SMEM);

    k_convert<<<dim3(CH, NB), 256>>>(X);          // 1 (X -> hi/lo + mean part)
    k_mean_final<<<2, 256>>>();                   // 2
    k_mean_final<<<2, 256>>>();                   // 3 (slot pad; idempotent)
    k_gram_mma<<<dim3(10, NB), 256, G_SMEM>>>();  // 4 <- ncu slot
    k_sigma<<<1024, 256>>>();
    k_trace<<<1, 512>>>();
    k_prep<<<1024, 256>>>();

    for (int t = 0; t < 10; t++) {
        const int pb = t & 1;
        k_ns_dual<<<dim3(8, 8, 2), 256>>>(pb);
        k_ns_combine<<<dim3(8, 8), 256>>>(pb);
    }
    k_rotP<<<dim3(8, 8), 256>>>(rot, 0);
    k_Msplit<<<1024, 256>>>();
    k_bias<<<2, 256>>>();

    k_out_mma<<<dim3(25, 4, NB), 256, O_SMEM>>>(out);
}